// round 3
// baseline (speedup 1.0000x reference)
#include <cuda_runtime.h>
#include <math.h>

#define POOL 7
#define C 256
#define CQ (C / 4)          // 64 float4 per pixel

typedef unsigned long long u64;

__device__ __forceinline__ u64 f32x2_mul(u64 a, u64 b) {
    u64 d; asm("mul.rn.f32x2 %0, %1, %2;" : "=l"(d) : "l"(a), "l"(b)); return d;
}
__device__ __forceinline__ u64 f32x2_fma(u64 a, u64 b, u64 c) {
    u64 d; asm("fma.rn.f32x2 %0, %1, %2, %3;" : "=l"(d) : "l"(a), "l"(b), "l"(c)); return d;
}
__device__ __forceinline__ u64 f32x2_pack(float v) {
    u64 d; asm("mov.b64 %0, {%1, %1};" : "=l"(d) : "f"(v)); return d;
}
__device__ __forceinline__ u64 bilerp2(u64 v00, u64 v01, u64 v10, u64 v11,
                                       u64 wtx2, u64 tx2, u64 wty2, u64 ty2) {
    u64 top = f32x2_fma(v01, tx2, f32x2_mul(v00, wtx2));
    u64 bot = f32x2_fma(v11, tx2, f32x2_mul(v10, wtx2));
    return f32x2_fma(bot, ty2, f32x2_mul(top, wty2));
}

// Grid: 2 blocks per ROI (channel halves). Block (32,7): warp = pooled row, lane = channel quad.
__global__ __launch_bounds__(224, 6)
void roi_align_kernel(const float* __restrict__ rois,
                      const int*   __restrict__ image_shape,
                      const float* __restrict__ p2,
                      const float* __restrict__ p3,
                      const float* __restrict__ p4,
                      const float* __restrict__ p5,
                      float* __restrict__ out,
                      int N)
{
    const int blk  = blockIdx.x;
    const int bn   = blk >> 1;          // ROI index
    const int half = blk & 1;           // channel half: quads [0,32) or [32,64)
    const int b    = bn / N;

    const float4 r = reinterpret_cast<const float4*>(rois)[bn];
    const float y1 = r.x, x1 = r.y, y2 = r.z, x2 = r.w;
    const float h = y2 - y1;
    const float w = x2 - x1;

    const float img_area = (float)(image_shape[0]) * (float)(image_shape[1]);
    const float scale = sqrtf(fmaxf(h * w, 1e-12f)) * (sqrtf(img_area) / 224.0f);
    int lvl = 4 + (int)rintf(log2f(scale));   // round-half-even == jnp.round
    lvl = min(max(lvl, 2), 5);

    const float* feat;
    int H;
    switch (lvl) {
        case 2:  feat = p2; H = 256; break;
        case 3:  feat = p3; H = 128; break;
        case 4:  feat = p4; H = 64;  break;
        default: feat = p5; H = 32;  break;
    }
    const float Hm1 = (float)(H - 1);
    const float Hm2 = (float)(H - 2);

    // Base for this block's channel half (64 floats = 16 quads... half*128 floats).
    feat += (size_t)b * (size_t)H * (size_t)H * C + half * (C / 2);

    const int lane = threadIdx.x;   // 0..31: channel quad within half
    const int py   = threadIdx.y;   // 0..6:  pooled row (warp-uniform)

    // ---- y coordinate (warp-uniform, once) ----
    const float gy  = (float)py * (1.0f / (POOL - 1));
    const float ysf = (y1 + gy * h) * Hm1;
    const float y0f = fminf(fmaxf(floorf(ysf), 0.0f), Hm2);
    const int   y0  = (int)y0f;
    const float ty  = fminf(fmaxf(ysf - y0f, 0.0f), 1.0f);
    const u64 wty2 = f32x2_pack(1.0f - ty);
    const u64 ty2  = f32x2_pack(ty);

    const float* row0 = feat + (size_t)y0 * H * C;
    const float* row1 = row0 + (size_t)H * C;

    // ---- precompute all 7 x coordinates (registers) ----
    int   x0a[POOL];
    float txa[POOL];
#pragma unroll
    for (int px = 0; px < POOL; ++px) {
        const float gx  = (float)px * (1.0f / (POOL - 1));
        const float xsf = (x1 + gx * w) * Hm1;
        const float x0f = fminf(fmaxf(floorf(xsf), 0.0f), Hm2);
        x0a[px] = (int)x0f;
        txa[px] = fminf(fmaxf(xsf - x0f, 0.0f), 1.0f);
    }

    // Output base: quad index = cell*64 + half*32 + lane
    float4* out_base = reinterpret_cast<float4*>(out + (size_t)bn * (POOL * POOL * C))
                       + half * 32 + lane;

#pragma unroll
    for (int px = 0; px < POOL; ++px) {
        const int xoff = x0a[px] * C;
        const ulonglong2* p0 = reinterpret_cast<const ulonglong2*>(row0 + xoff) + lane;
        const ulonglong2* p1 = reinterpret_cast<const ulonglong2*>(row1 + xoff) + lane;

        // 4 coalesced LDG.128; addresses depend only on precomputed ints.
        const ulonglong2 v00 = p0[0];
        const ulonglong2 v01 = p0[CQ];   // +C floats = +64 float4
        const ulonglong2 v10 = p1[0];
        const ulonglong2 v11 = p1[CQ];

        const float tx  = txa[px];
        const u64 wtx2 = f32x2_pack(1.0f - tx);
        const u64 tx2  = f32x2_pack(tx);

        ulonglong2 res;
        res.x = bilerp2(v00.x, v01.x, v10.x, v11.x, wtx2, tx2, wty2, ty2);
        res.y = bilerp2(v00.y, v01.y, v10.y, v11.y, wtx2, tx2, wty2, ty2);

        __stcs(out_base + (size_t)(py * POOL + px) * CQ,
               *reinterpret_cast<float4*>(&res));
    }
}

extern "C" void kernel_launch(void* const* d_in, const int* in_sizes, int n_in,
                              void* d_out, int out_size)
{
    const float* rois        = (const float*)d_in[0];
    const int*   image_shape = (const int*)  d_in[1];
    const float* p2          = (const float*)d_in[2];
    const float* p3          = (const float*)d_in[3];
    const float* p4          = (const float*)d_in[4];
    const float* p5          = (const float*)d_in[5];
    float*       out         = (float*)d_out;

    const int B = in_sizes[2] / (256 * 256 * 256);
    const int N = in_sizes[0] / (4 * B);

    dim3 block(32, 7);
    dim3 grid(B * N * 2);
    roi_align_kernel<<<grid, block>>>(rois, image_shape, p2, p3, p4, p5, out, N);
}